// round 3
// baseline (speedup 1.0000x reference)
#include <cuda_runtime.h>
#include <math.h>

#define BATCH 8
#define SEQ   2048
#define HID   1024
#define HS    64
#define MTOT  (BATCH*SEQ)

// scratch for q,k,v projections (4 MB each)
__device__ float g_q[MTOT*HS];
__device__ float g_k[MTOT*HS];
__device__ float g_v[MTOT*HS];

// ---------------------------------------------------------------------------
// QKV projection: out[m][n] = sum_k x[m][k] * W[k][n]
// M=16384, N=64, K=1024.  Block: 128 rows x 64 cols, 256 threads,
// per-thread 8x4 register tile, K-tile 16.
// ---------------------------------------------------------------------------
__global__ __launch_bounds__(256) void qkv_kernel(
    const float* __restrict__ x,
    const float* __restrict__ Wq,
    const float* __restrict__ Wk,
    const float* __restrict__ Wv)
{
    const float* W   = (blockIdx.y == 0) ? Wq  : (blockIdx.y == 1) ? Wk  : Wv;
    float*       out = (blockIdx.y == 0) ? g_q : (blockIdx.y == 1) ? g_k : g_v;

    __shared__ float xs[16][128];   // transposed x tile: xs[kk][row]
    __shared__ float ws[16][64];    // ws[kk][col]

    const int t  = threadIdx.x;
    const int ty = t >> 4;          // 0..15 -> row group (8 rows)
    const int tx = t & 15;          // 0..15 -> col group (4 cols)
    const int m0 = blockIdx.x * 128;

    float acc[8][4];
    #pragma unroll
    for (int i = 0; i < 8; i++)
        #pragma unroll
        for (int j = 0; j < 4; j++) acc[i][j] = 0.f;

    for (int k0 = 0; k0 < HID; k0 += 16) {
        // load x tile (128 rows x 16 cols) transposed
        #pragma unroll
        for (int half = 0; half < 2; half++) {
            int row = (t >> 2) + half * 64;
            int kk  = (t & 3) * 4;
            float4 v = *reinterpret_cast<const float4*>(
                &x[(size_t)(m0 + row) * HID + k0 + kk]);
            xs[kk + 0][row] = v.x;
            xs[kk + 1][row] = v.y;
            xs[kk + 2][row] = v.z;
            xs[kk + 3][row] = v.w;
        }
        // load W tile (16 rows x 64 cols)
        {
            int r = t >> 4;
            int c = (t & 15) * 4;
            *reinterpret_cast<float4*>(&ws[r][c]) =
                *reinterpret_cast<const float4*>(&W[(size_t)(k0 + r) * HS + c]);
        }
        __syncthreads();

        #pragma unroll
        for (int kk = 0; kk < 16; kk++) {
            float4 a0 = *reinterpret_cast<float4*>(&xs[kk][ty * 8]);
            float4 a1 = *reinterpret_cast<float4*>(&xs[kk][ty * 8 + 4]);
            float4 b4 = *reinterpret_cast<float4*>(&ws[kk][tx * 4]);
            float a[8] = {a0.x, a0.y, a0.z, a0.w, a1.x, a1.y, a1.z, a1.w};
            float b[4] = {b4.x, b4.y, b4.z, b4.w};
            #pragma unroll
            for (int i = 0; i < 8; i++)
                #pragma unroll
                for (int j = 0; j < 4; j++)
                    acc[i][j] += a[i] * b[j];
        }
        __syncthreads();
    }

    #pragma unroll
    for (int i = 0; i < 8; i++) {
        float4 o = make_float4(acc[i][0], acc[i][1], acc[i][2], acc[i][3]);
        *reinterpret_cast<float4*>(
            &out[(size_t)(m0 + ty * 8 + i) * HS + tx * 4]) = o;
    }
}

// ---------------------------------------------------------------------------
// Causal flash attention.  BQ=BK=64, 256 threads, 4x4 register tiles,
// online softmax parallelized 4 threads per row (shfl reductions).
// ---------------------------------------------------------------------------
#define BQ  64
#define BK  64
#define PAD 68
#define NEG_BIG (-1e30f)

__global__ __launch_bounds__(256) void attn_kernel(float* __restrict__ out)
{
    extern __shared__ float sm[];
    float* Qs   = sm;                 // 64*68
    float* Ks   = Qs + BQ * PAD;      // 64*68
    float* Vs   = Ks + BK * PAD;      // 64*68
    float* Ss   = Vs + BK * PAD;      // 64*68
    float* l_s  = Ss + BQ * PAD;      // 64
    float* al_s = l_s + BQ;           // 64

    const int t  = threadIdx.x;
    const int b  = blockIdx.y;
    const int bx = blockIdx.x;
    // interleave big/small causal tiles to balance SM load
    const int nqt = gridDim.x;
    const int qt  = (bx & 1) ? (nqt - 1 - (bx >> 1)) : (bx >> 1);
    const int q0  = qt * BQ;
    const float scale = 0.03125f;     // 1024^-0.5

    // load Q tile, pre-scaled
    {
        const float* qbase = g_q + ((size_t)b * SEQ + q0) * HS;
        for (int rep = 0; rep < 4; rep++) {
            int lin = rep * 256 + t;
            int row = lin >> 4;
            int c   = (lin & 15) * 4;
            float4 v = *reinterpret_cast<const float4*>(qbase + row * HS + c);
            v.x *= scale; v.y *= scale; v.z *= scale; v.w *= scale;
            *reinterpret_cast<float4*>(&Qs[row * PAD + c]) = v;
        }
    }

    const int tr = (t >> 4) * 4;      // row base within tile (GEMM mapping)
    const int tc = (t & 15) * 4;      // col base within tile

    // softmax mapping: 4 threads per row, consecutive lanes
    const int srow_id = t >> 2;       // 0..63
    const int sseg    = (t & 3) * 16; // 16 columns each

    float o[4][4];
    #pragma unroll
    for (int i = 0; i < 4; i++)
        #pragma unroll
        for (int j = 0; j < 4; j++) o[i][j] = 0.f;

    float m_old = NEG_BIG;   // per-row state, replicated in 4 threads
    float lsum  = 0.f;

    for (int jt = 0; jt <= qt; jt++) {
        const int kv0 = jt * BK;
        __syncthreads();   // prior PV done + Q visible before (re)loading K/V

        {
            const float* kb = g_k + ((size_t)b * SEQ + kv0) * HS;
            const float* vb = g_v + ((size_t)b * SEQ + kv0) * HS;
            for (int rep = 0; rep < 4; rep++) {
                int lin = rep * 256 + t;
                int row = lin >> 4;
                int c   = (lin & 15) * 4;
                *reinterpret_cast<float4*>(&Ks[row * PAD + c]) =
                    *reinterpret_cast<const float4*>(kb + row * HS + c);
                *reinterpret_cast<float4*>(&Vs[row * PAD + c]) =
                    *reinterpret_cast<const float4*>(vb + row * HS + c);
            }
        }
        __syncthreads();

        // S = Q * K^T  (4x4 per thread)
        float s[4][4];
        #pragma unroll
        for (int i = 0; i < 4; i++)
            #pragma unroll
            for (int j = 0; j < 4; j++) s[i][j] = 0.f;

        #pragma unroll
        for (int d = 0; d < HS; d += 4) {
            float4 q4[4], k4[4];
            #pragma unroll
            for (int i = 0; i < 4; i++)
                q4[i] = *reinterpret_cast<float4*>(&Qs[(tr + i) * PAD + d]);
            #pragma unroll
            for (int j = 0; j < 4; j++)
                k4[j] = *reinterpret_cast<float4*>(&Ks[(tc + j) * PAD + d]);
            #pragma unroll
            for (int i = 0; i < 4; i++)
                #pragma unroll
                for (int j = 0; j < 4; j++)
                    s[i][j] += q4[i].x * k4[j].x + q4[i].y * k4[j].y +
                               q4[i].z * k4[j].z + q4[i].w * k4[j].w;
        }

        const bool diag = (jt == qt);
        #pragma unroll
        for (int i = 0; i < 4; i++) {
            if (diag) {
                int qr = q0 + tr + i;
                #pragma unroll
                for (int j = 0; j < 4; j++)
                    if (kv0 + tc + j > qr) s[i][j] = NEG_BIG;
            }
            float4 sv = make_float4(s[i][0], s[i][1], s[i][2], s[i][3]);
            *reinterpret_cast<float4*>(&Ss[(tr + i) * PAD + tc]) = sv;
        }
        __syncthreads();

        // online softmax: 4 threads per row, 16 cols each, shfl reduce
        {
            float* srow = &Ss[srow_id * PAD + sseg];
            float mx = NEG_BIG;
            #pragma unroll
            for (int c2 = 0; c2 < 16; c2++) mx = fmaxf(mx, srow[c2]);
            mx = fmaxf(mx, __shfl_xor_sync(0xffffffffu, mx, 1));
            mx = fmaxf(mx, __shfl_xor_sync(0xffffffffu, mx, 2));
            mx = fmaxf(mx, m_old);

            float sum = 0.f;
            #pragma unroll
            for (int c2 = 0; c2 < 16; c2++) {
                float p = __expf(srow[c2] - mx);
                srow[c2] = p;
                sum += p;
            }
            sum += __shfl_xor_sync(0xffffffffu, sum, 1);
            sum += __shfl_xor_sync(0xffffffffu, sum, 2);

            float alpha = __expf(m_old - mx);
            lsum = lsum * alpha + sum;
            m_old = mx;
            if ((t & 3) == 0) al_s[srow_id] = alpha;
        }
        __syncthreads();

        // rescale O and accumulate O += P * V
        float al[4];
        #pragma unroll
        for (int i = 0; i < 4; i++) al[i] = al_s[tr + i];
        #pragma unroll
        for (int i = 0; i < 4; i++)
            #pragma unroll
            for (int j = 0; j < 4; j++) o[i][j] *= al[i];

        #pragma unroll
        for (int kk = 0; kk < BK; kk += 4) {
            float4 v0 = *reinterpret_cast<float4*>(&Vs[(kk + 0) * PAD + tc]);
            float4 v1 = *reinterpret_cast<float4*>(&Vs[(kk + 1) * PAD + tc]);
            float4 v2 = *reinterpret_cast<float4*>(&Vs[(kk + 2) * PAD + tc]);
            float4 v3 = *reinterpret_cast<float4*>(&Vs[(kk + 3) * PAD + tc]);
            #pragma unroll
            for (int i = 0; i < 4; i++) {
                float4 p = *reinterpret_cast<float4*>(&Ss[(tr + i) * PAD + kk]);
                o[i][0] += p.x * v0.x + p.y * v1.x + p.z * v2.x + p.w * v3.x;
                o[i][1] += p.x * v0.y + p.y * v1.y + p.z * v2.y + p.w * v3.y;
                o[i][2] += p.x * v0.z + p.y * v1.z + p.z * v2.z + p.w * v3.z;
                o[i][3] += p.x * v0.w + p.y * v1.w + p.z * v2.w + p.w * v3.w;
            }
        }
    }

    if ((t & 3) == 0) l_s[srow_id] = lsum;
    __syncthreads();

    #pragma unroll
    for (int i = 0; i < 4; i++) {
        float inv = 1.f / l_s[tr + i];
        float4 ov = make_float4(o[i][0] * inv, o[i][1] * inv,
                                o[i][2] * inv, o[i][3] * inv);
        *reinterpret_cast<float4*>(
            &out[((size_t)b * SEQ + q0 + tr + i) * HS + tc]) = ov;
    }
}

#define ATTN_SMEM ((4 * BQ * PAD + 2 * BQ) * (int)sizeof(float))

extern "C" void kernel_launch(void* const* d_in, const int* in_sizes, int n_in,
                              void* d_out, int out_size)
{
    const float* x  = (const float*)d_in[0];
    const float* Wq = (const float*)d_in[1];
    const float* Wk = (const float*)d_in[2];
    const float* Wv = (const float*)d_in[3];
    float* out = (float*)d_out;

    qkv_kernel<<<dim3(MTOT / 128, 3), 256>>>(x, Wq, Wk, Wv);

    (void)cudaFuncSetAttribute(attn_kernel,
                               cudaFuncAttributeMaxDynamicSharedMemorySize,
                               ATTN_SMEM);
    attn_kernel<<<dim3(SEQ / BQ, BATCH), 256, ATTN_SMEM>>>(out);
}

// round 5
// speedup vs baseline: 1.4410x; 1.4410x over previous
#include <cuda_runtime.h>
#include <math.h>

#define BATCH 8
#define SEQ   2048
#define HID   1024
#define HS    64
#define MTOT  (BATCH*SEQ)

// scratch for q,k,v projections (4 MB each)
__device__ float g_q[MTOT*HS];
__device__ float g_k[MTOT*HS];
__device__ float g_v[MTOT*HS];

// ---------------------------------------------------------------------------
// QKV projection: out[m][n] = sum_k x[m][k] * W[k][n]
// M=16384, N=64, K=1024.  128x64 block tile, 256 threads, 8x4 per thread.
// Measured at the fp32 FFMA roofline (~182us) - unchanged.
// ---------------------------------------------------------------------------
__global__ __launch_bounds__(256) void qkv_kernel(
    const float* __restrict__ x,
    const float* __restrict__ Wq,
    const float* __restrict__ Wk,
    const float* __restrict__ Wv)
{
    const float* W   = (blockIdx.y == 0) ? Wq  : (blockIdx.y == 1) ? Wk  : Wv;
    float*       out = (blockIdx.y == 0) ? g_q : (blockIdx.y == 1) ? g_k : g_v;

    __shared__ float xs[16][128];   // transposed x tile: xs[kk][row]
    __shared__ float ws[16][64];    // ws[kk][col]

    const int t  = threadIdx.x;
    const int ty = t >> 4;
    const int tx = t & 15;
    const int m0 = blockIdx.x * 128;

    float acc[8][4];
    #pragma unroll
    for (int i = 0; i < 8; i++)
        #pragma unroll
        for (int j = 0; j < 4; j++) acc[i][j] = 0.f;

    for (int k0 = 0; k0 < HID; k0 += 16) {
        #pragma unroll
        for (int half = 0; half < 2; half++) {
            int row = (t >> 2) + half * 64;
            int kk  = (t & 3) * 4;
            float4 v = *reinterpret_cast<const float4*>(
                &x[(size_t)(m0 + row) * HID + k0 + kk]);
            xs[kk + 0][row] = v.x;
            xs[kk + 1][row] = v.y;
            xs[kk + 2][row] = v.z;
            xs[kk + 3][row] = v.w;
        }
        {
            int r = t >> 4;
            int c = (t & 15) * 4;
            *reinterpret_cast<float4*>(&ws[r][c]) =
                *reinterpret_cast<const float4*>(&W[(size_t)(k0 + r) * HS + c]);
        }
        __syncthreads();

        #pragma unroll
        for (int kk = 0; kk < 16; kk++) {
            float4 a0 = *reinterpret_cast<float4*>(&xs[kk][ty * 8]);
            float4 a1 = *reinterpret_cast<float4*>(&xs[kk][ty * 8 + 4]);
            float4 b4 = *reinterpret_cast<float4*>(&ws[kk][tx * 4]);
            float a[8] = {a0.x, a0.y, a0.z, a0.w, a1.x, a1.y, a1.z, a1.w};
            float b[4] = {b4.x, b4.y, b4.z, b4.w};
            #pragma unroll
            for (int i = 0; i < 8; i++)
                #pragma unroll
                for (int j = 0; j < 4; j++)
                    acc[i][j] += a[i] * b[j];
        }
        __syncthreads();
    }

    #pragma unroll
    for (int i = 0; i < 8; i++) {
        float4 o = make_float4(acc[i][0], acc[i][1], acc[i][2], acc[i][3]);
        *reinterpret_cast<float4*>(
            &out[(size_t)(m0 + ty * 8 + i) * HS + tx * 4]) = o;
    }
}

// ---------------------------------------------------------------------------
// Causal flash attention.  BQ=BK=64, 256 threads, 4x4 register tiles.
// K/V in XOR-swizzled smem (conflict-free column reads), in-register
// softmax via shfl over the 16-lane row group, 3 barriers/tile,
// schedule permutation balancing co-resident CTA pairs (l, l+148).
// ---------------------------------------------------------------------------
#define BQ  64
#define BK  64
#define NEG_BIG (-1e30f)

// swizzle: row r, 4-float chunk c4 stored at chunk (c4 ^ swf(r))
__device__ __forceinline__ int swf(int r) {
    return (((r >> 2) * 5) + (r & 3)) & 15;
}

__global__ __launch_bounds__(256) void attn_kernel(float* __restrict__ out)
{
    extern __shared__ float sm[];
    float* Qs = sm;            // 64x64, unswizzled (reads are broadcasts)
    float* Ks = Qs + 4096;     // 64x64, swizzled
    float* Vs = Ks + 4096;     // 64x64, swizzled
    float* Ps = Vs + 4096;     // 64x64, unswizzled (reads are broadcasts)

    const int t = threadIdx.x;
    const int b = blockIdx.y;
    const int x = blockIdx.x;
    // balance co-resident CTA pairs (linear l pairs with l+148 -> x with (x+20)%32):
    // pair sums ~19..31 tiles, singleton SMs get <=32, critical SM ~33 tiles.
    const int qt = (x < 8) ? x : (x < 12) ? x + 8 : (x < 24) ? 43 - x : 39 - x;
    const int q0 = qt * BQ;
    const float scale = 0.03125f;     // 1024^-0.5

    // load Q tile, pre-scaled
    {
        const float* qbase = g_q + ((size_t)b * SEQ + q0) * HS;
        for (int rep = 0; rep < 4; rep++) {
            int lin = rep * 256 + t;
            int row = lin >> 4;
            int c   = (lin & 15) * 4;
            float4 v = *reinterpret_cast<const float4*>(qbase + row * HS + c);
            v.x *= scale; v.y *= scale; v.z *= scale; v.w *= scale;
            *reinterpret_cast<float4*>(&Qs[row * 64 + c]) = v;
        }
    }

    const int ty = t >> 4;
    const int tx = t & 15;
    const int tr = ty * 4;
    const int tc = tx * 4;

    // per-thread swizzle constants for K reads (rows tc..tc+3)
    int krow[4], kf[4];
    #pragma unroll
    for (int j = 0; j < 4; j++) { krow[j] = (tc + j) * 64; kf[j] = swf(tc + j); }

    float o[4][4];
    #pragma unroll
    for (int i = 0; i < 4; i++)
        #pragma unroll
        for (int j = 0; j < 4; j++) o[i][j] = 0.f;

    float m[4], l[4];
    #pragma unroll
    for (int i = 0; i < 4; i++) { m[i] = NEG_BIG; l[i] = 0.f; }

    for (int jt = 0; jt <= qt; jt++) {
        const int kv0 = jt * BK;
        __syncthreads();   // prev PV done before K/V/P overwrite

        {
            const float* kb = g_k + ((size_t)b * SEQ + kv0) * HS;
            const float* vb = g_v + ((size_t)b * SEQ + kv0) * HS;
            for (int rep = 0; rep < 4; rep++) {
                int lin = rep * 256 + t;
                int row = lin >> 4;
                int c4  = lin & 15;
                int sw  = row * 64 + ((c4 ^ swf(row)) << 2);
                *reinterpret_cast<float4*>(&Ks[sw]) =
                    *reinterpret_cast<const float4*>(kb + row * HS + c4 * 4);
                *reinterpret_cast<float4*>(&Vs[sw]) =
                    *reinterpret_cast<const float4*>(vb + row * HS + c4 * 4);
            }
        }
        __syncthreads();

        // S = Q * K^T  (4x4 per thread)
        float s[4][4];
        #pragma unroll
        for (int i = 0; i < 4; i++)
            #pragma unroll
            for (int j = 0; j < 4; j++) s[i][j] = 0.f;

        #pragma unroll
        for (int d = 0; d < HS; d += 4) {
            const int c4 = d >> 2;
            float4 q4[4], k4[4];
            #pragma unroll
            for (int i = 0; i < 4; i++)
                q4[i] = *reinterpret_cast<float4*>(&Qs[(tr + i) * 64 + d]);
            #pragma unroll
            for (int j = 0; j < 4; j++)
                k4[j] = *reinterpret_cast<float4*>(
                    &Ks[krow[j] + ((c4 ^ kf[j]) << 2)]);
            #pragma unroll
            for (int i = 0; i < 4; i++)
                #pragma unroll
                for (int j = 0; j < 4; j++)
                    s[i][j] += q4[i].x * k4[j].x + q4[i].y * k4[j].y +
                               q4[i].z * k4[j].z + q4[i].w * k4[j].w;
        }

        if (jt == qt) {
            #pragma unroll
            for (int i = 0; i < 4; i++) {
                int qr = q0 + tr + i;
                #pragma unroll
                for (int j = 0; j < 4; j++)
                    if (kv0 + tc + j > qr) s[i][j] = NEG_BIG;
            }
        }

        // in-register online softmax: shfl over 16-lane row group
        #pragma unroll
        for (int i = 0; i < 4; i++) {
            float mx = fmaxf(fmaxf(s[i][0], s[i][1]), fmaxf(s[i][2], s[i][3]));
            mx = fmaxf(mx, __shfl_xor_sync(0xffffffffu, mx, 1));
            mx = fmaxf(mx, __shfl_xor_sync(0xffffffffu, mx, 2));
            mx = fmaxf(mx, __shfl_xor_sync(0xffffffffu, mx, 4));
            mx = fmaxf(mx, __shfl_xor_sync(0xffffffffu, mx, 8));
            float mnew = fmaxf(m[i], mx);
            float p0 = __expf(s[i][0] - mnew);
            float p1 = __expf(s[i][1] - mnew);
            float p2 = __expf(s[i][2] - mnew);
            float p3 = __expf(s[i][3] - mnew);
            float sum = (p0 + p1) + (p2 + p3);
            sum += __shfl_xor_sync(0xffffffffu, sum, 1);
            sum += __shfl_xor_sync(0xffffffffu, sum, 2);
            sum += __shfl_xor_sync(0xffffffffu, sum, 4);
            sum += __shfl_xor_sync(0xffffffffu, sum, 8);
            float a = __expf(m[i] - mnew);
            l[i] = l[i] * a + sum;
            m[i] = mnew;
            o[i][0] *= a; o[i][1] *= a; o[i][2] *= a; o[i][3] *= a;
            *reinterpret_cast<float4*>(&Ps[(tr + i) * 64 + tc]) =
                make_float4(p0, p1, p2, p3);
        }
        __syncthreads();

        // O += P * V
        #pragma unroll
        for (int kk = 0; kk < BK; kk += 4) {
            const int b5 = ((kk >> 2) * 5) & 15;
            float4 v0 = *reinterpret_cast<float4*>(
                &Vs[(kk + 0) * 64 + ((tx ^ ( b5      & 15)) << 2)]);
            float4 v1 = *reinterpret_cast<float4*>(
                &Vs[(kk + 1) * 64 + ((tx ^ ((b5 + 1) & 15)) << 2)]);
            float4 v2 = *reinterpret_cast<float4*>(
                &Vs[(kk + 2) * 64 + ((tx ^ ((b5 + 2) & 15)) << 2)]);
            float4 v3 = *reinterpret_cast<float4*>(
                &Vs[(kk + 3) * 64 + ((tx ^ ((b5 + 3) & 15)) << 2)]);
            #pragma unroll
            for (int i = 0; i < 4; i++) {
                float4 p = *reinterpret_cast<float4*>(&Ps[(tr + i) * 64 + kk]);
                o[i][0] += p.x * v0.x + p.y * v1.x + p.z * v2.x + p.w * v3.x;
                o[i][1] += p.x * v0.y + p.y * v1.y + p.z * v2.y + p.w * v3.y;
                o[i][2] += p.x * v0.z + p.y * v1.z + p.z * v2.z + p.w * v3.z;
                o[i][3] += p.x * v0.w + p.y * v1.w + p.z * v2.w + p.w * v3.w;
            }
        }
    }

    #pragma unroll
    for (int i = 0; i < 4; i++) {
        float inv = 1.f / l[i];
        float4 ov = make_float4(o[i][0] * inv, o[i][1] * inv,
                                o[i][2] * inv, o[i][3] * inv);
        *reinterpret_cast<float4*>(
            &out[((size_t)b * SEQ + q0 + tr + i) * HS + tc]) = ov;
    }
}

#define ATTN_SMEM (4 * 64 * 64 * (int)sizeof(float))

extern "C" void kernel_launch(void* const* d_in, const int* in_sizes, int n_in,
                              void* d_out, int out_size)
{
    const float* x  = (const float*)d_in[0];
    const float* Wq = (const float*)d_in[1];
    const float* Wk = (const float*)d_in[2];
    const float* Wv = (const float*)d_in[3];
    float* out = (float*)d_out;

    qkv_kernel<<<dim3(MTOT / 128, 3), 256>>>(x, Wq, Wk, Wv);

    (void)cudaFuncSetAttribute(attn_kernel,
                               cudaFuncAttributeMaxDynamicSharedMemorySize,
                               ATTN_SMEM);
    attn_kernel<<<dim3(SEQ / BQ, BATCH), 256, ATTN_SMEM>>>(out);
}

// round 6
// speedup vs baseline: 3.5291x; 2.4491x over previous
#include <cuda_runtime.h>
#include <math.h>

#define BATCH 8
#define SEQ   2048
#define HID   1024
#define HS    64
#define MTOT  (BATCH*SEQ)

// q,k,v stored as tf32 bit patterns (q pre-scaled by 1024^-0.5)
__device__ unsigned int g_q[MTOT*HS];
__device__ unsigned int g_k[MTOT*HS];
__device__ unsigned int g_v[MTOT*HS];

__device__ __forceinline__ unsigned int f2tf32(float f) {
    unsigned int u;
    asm("cvt.rna.tf32.f32 %0, %1;" : "=r"(u) : "f"(f));
    return u;
}

// D += A(16x8) * B(8x8), tf32 inputs, f32 accum
__device__ __forceinline__ void mma_tf32(float* d, const unsigned int* a,
                                         const unsigned int* b) {
    asm("mma.sync.aligned.m16n8k8.row.col.f32.tf32.tf32.f32 "
        "{%0,%1,%2,%3}, {%4,%5,%6,%7}, {%8,%9}, {%0,%1,%2,%3};"
        : "+f"(d[0]), "+f"(d[1]), "+f"(d[2]), "+f"(d[3])
        : "r"(a[0]), "r"(a[1]), "r"(a[2]), "r"(a[3]),
          "r"(b[0]), "r"(b[1]));
}

// ---------------------------------------------------------------------------
// QKV projection via tf32 MMA: out[m][n] = sum_k x[m][k]*W[k][n], as tf32 bits.
// CTA tile 128x64, 8 warps (4m x 2n), warp tile 32x32, K-tile 32.
// ---------------------------------------------------------------------------
#define XS_STR 36
#define WS_STR 72

__global__ __launch_bounds__(256) void qkv_kernel(
    const float* __restrict__ x,
    const float* __restrict__ Wq,
    const float* __restrict__ Wk,
    const float* __restrict__ Wv)
{
    __shared__ unsigned int Xs[128 * XS_STR];
    __shared__ unsigned int Ws[32 * WS_STR];

    const float* W = (blockIdx.y == 0) ? Wq : (blockIdx.y == 1) ? Wk : Wv;
    unsigned int* out = (blockIdx.y == 0) ? g_q : (blockIdx.y == 1) ? g_k : g_v;

    const int t    = threadIdx.x;
    const int wid  = t >> 5;
    const int lane = t & 31;
    const int q    = lane >> 2;   // 0..7
    const int qi   = lane & 3;    // 0..3
    const int wm   = wid >> 1;    // 0..3 -> 32-row group
    const int wn   = wid & 1;     // 0..1 -> 32-col group
    const int m0   = blockIdx.x * 128;

    float acc[2][4][4];
    #pragma unroll
    for (int mt = 0; mt < 2; mt++)
        #pragma unroll
        for (int nt = 0; nt < 4; nt++)
            #pragma unroll
            for (int j = 0; j < 4; j++) acc[mt][nt][j] = 0.f;

    for (int k0 = 0; k0 < HID; k0 += 32) {
        // stage X tile 128x32 (cvt to tf32)
        #pragma unroll
        for (int rep = 0; rep < 4; rep++) {
            int lin = rep * 256 + t;
            int row = lin >> 3;
            int c4  = lin & 7;
            float4 v = *reinterpret_cast<const float4*>(
                &x[(size_t)(m0 + row) * HID + k0 + c4 * 4]);
            uint4 u = make_uint4(f2tf32(v.x), f2tf32(v.y),
                                 f2tf32(v.z), f2tf32(v.w));
            *reinterpret_cast<uint4*>(&Xs[row * XS_STR + c4 * 4]) = u;
        }
        // stage W tile 32x64
        #pragma unroll
        for (int rep = 0; rep < 2; rep++) {
            int lin = rep * 256 + t;
            int row = lin >> 4;
            int c4  = lin & 15;
            float4 v = *reinterpret_cast<const float4*>(
                &W[(size_t)(k0 + row) * HS + c4 * 4]);
            uint4 u = make_uint4(f2tf32(v.x), f2tf32(v.y),
                                 f2tf32(v.z), f2tf32(v.w));
            *reinterpret_cast<uint4*>(&Ws[row * WS_STR + c4 * 4]) = u;
        }
        __syncthreads();

        #pragma unroll
        for (int ks = 0; ks < 4; ks++) {
            const int kk = ks * 8;
            unsigned int a[2][4];
            #pragma unroll
            for (int mt = 0; mt < 2; mt++) {
                int r0 = wm * 32 + mt * 16;
                a[mt][0] = Xs[(r0 + q    ) * XS_STR + kk + qi    ];
                a[mt][1] = Xs[(r0 + q + 8) * XS_STR + kk + qi    ];
                a[mt][2] = Xs[(r0 + q    ) * XS_STR + kk + qi + 4];
                a[mt][3] = Xs[(r0 + q + 8) * XS_STR + kk + qi + 4];
            }
            #pragma unroll
            for (int nt = 0; nt < 4; nt++) {
                int n0 = wn * 32 + nt * 8;
                unsigned int b[2];
                b[0] = Ws[(kk + qi    ) * WS_STR + n0 + q];
                b[1] = Ws[(kk + qi + 4) * WS_STR + n0 + q];
                mma_tf32(acc[0][nt], a[0], b);
                mma_tf32(acc[1][nt], a[1], b);
            }
        }
        __syncthreads();
    }

    const float scl = (blockIdx.y == 0) ? 0.03125f : 1.0f;  // fold 1024^-0.5 into Q
    #pragma unroll
    for (int mt = 0; mt < 2; mt++) {
        int r0 = m0 + wm * 32 + mt * 16 + q;
        #pragma unroll
        for (int nt = 0; nt < 4; nt++) {
            int c0 = wn * 32 + nt * 8 + qi * 2;
            out[(size_t)r0 * HS + c0    ]       = f2tf32(acc[mt][nt][0] * scl);
            out[(size_t)r0 * HS + c0 + 1]       = f2tf32(acc[mt][nt][1] * scl);
            out[(size_t)(r0 + 8) * HS + c0    ] = f2tf32(acc[mt][nt][2] * scl);
            out[(size_t)(r0 + 8) * HS + c0 + 1] = f2tf32(acc[mt][nt][3] * scl);
        }
    }
}

// ---------------------------------------------------------------------------
// Causal flash attention via tf32 MMA.  BQ=BK=64, 128 threads (4 warps x 16
// rows).  Q fragments preloaded to registers; K/V/P staged in smem with
// conflict-free strides; softmax on C-fragments (2 intra-quad shfls/row).
// ---------------------------------------------------------------------------
#define KS_STR 68
#define VS_STR 72
#define PS_STR 68
#define NEG_BIG (-1e30f)

#define ATTN_SMEM ((64*KS_STR + 64*VS_STR + 64*PS_STR) * (int)sizeof(unsigned int))

__global__ __launch_bounds__(128) void attn_kernel(float* __restrict__ out)
{
    extern __shared__ unsigned int smu[];
    unsigned int* Ks = smu;                // 64 x 68
    unsigned int* Vs = Ks + 64 * KS_STR;   // 64 x 72
    unsigned int* Ps = Vs + 64 * VS_STR;   // 64 x 68 (also Q staging)

    const int t    = threadIdx.x;
    const int wid  = t >> 5;      // 0..3 -> 16-row group
    const int lane = t & 31;
    const int q    = lane >> 2;
    const int qi   = lane & 3;
    const int b    = blockIdx.y;
    const int x    = blockIdx.x;
    // balance co-resident CTA pairs (x pairs with (x+20)%32)
    const int qt = (x < 8) ? x : (x < 12) ? x + 8 : (x < 24) ? 43 - x : 39 - x;
    const int q0 = qt * 64;

    // stage Q tile then preload fragments (reused across all KV tiles)
    {
        const unsigned int* qb = g_q + ((size_t)b * SEQ + q0) * HS;
        #pragma unroll
        for (int rep = 0; rep < 8; rep++) {
            int lin = rep * 128 + t;
            int row = lin >> 4;
            int c4  = lin & 15;
            *reinterpret_cast<uint4*>(&Ps[row * PS_STR + c4 * 4]) =
                *reinterpret_cast<const uint4*>(qb + row * HS + c4 * 4);
        }
    }
    __syncthreads();

    unsigned int qa[8][4];
    {
        const int r0 = wid * 16 + q;
        #pragma unroll
        for (int ks = 0; ks < 8; ks++) {
            const int kk = ks * 8;
            qa[ks][0] = Ps[(r0    ) * PS_STR + kk + qi    ];
            qa[ks][1] = Ps[(r0 + 8) * PS_STR + kk + qi    ];
            qa[ks][2] = Ps[(r0    ) * PS_STR + kk + qi + 4];
            qa[ks][3] = Ps[(r0 + 8) * PS_STR + kk + qi + 4];
        }
    }

    float o[8][4];
    #pragma unroll
    for (int nt = 0; nt < 8; nt++)
        #pragma unroll
        for (int j = 0; j < 4; j++) o[nt][j] = 0.f;
    float m0r = NEG_BIG, m1r = NEG_BIG, l0 = 0.f, l1 = 0.f;

    for (int jt = 0; jt <= qt; jt++) {
        const int kv0 = jt * 64;
        __syncthreads();   // prior PV reads done before overwriting K/V (and Q stage read)

        {
            const unsigned int* kb = g_k + ((size_t)b * SEQ + kv0) * HS;
            const unsigned int* vb = g_v + ((size_t)b * SEQ + kv0) * HS;
            #pragma unroll
            for (int rep = 0; rep < 8; rep++) {
                int lin = rep * 128 + t;
                int row = lin >> 4;
                int c4  = lin & 15;
                *reinterpret_cast<uint4*>(&Ks[row * KS_STR + c4 * 4]) =
                    *reinterpret_cast<const uint4*>(kb + row * HS + c4 * 4);
                *reinterpret_cast<uint4*>(&Vs[row * VS_STR + c4 * 4]) =
                    *reinterpret_cast<const uint4*>(vb + row * HS + c4 * 4);
            }
        }
        __syncthreads();

        // S = Q * K^T : warp computes 16x64
        float s[8][4];
        #pragma unroll
        for (int nt = 0; nt < 8; nt++)
            #pragma unroll
            for (int j = 0; j < 4; j++) s[nt][j] = 0.f;

        #pragma unroll
        for (int ks = 0; ks < 8; ks++) {
            const int kk = ks * 8;
            #pragma unroll
            for (int nt = 0; nt < 8; nt++) {
                unsigned int kb2[2];
                kb2[0] = Ks[(nt * 8 + q) * KS_STR + kk + qi    ];
                kb2[1] = Ks[(nt * 8 + q) * KS_STR + kk + qi + 4];
                mma_tf32(s[nt], qa[ks], kb2);
            }
        }

        if (jt == qt) {   // causal mask on diagonal tile
            const int rg0 = q0 + wid * 16 + q;
            #pragma unroll
            for (int nt = 0; nt < 8; nt++) {
                const int cg = kv0 + nt * 8 + qi * 2;
                if (cg     > rg0    ) s[nt][0] = NEG_BIG;
                if (cg + 1 > rg0    ) s[nt][1] = NEG_BIG;
                if (cg     > rg0 + 8) s[nt][2] = NEG_BIG;
                if (cg + 1 > rg0 + 8) s[nt][3] = NEG_BIG;
            }
        }

        // online softmax on fragments: rows r0=wid*16+q and r0+8
        float mx0 = NEG_BIG, mx1 = NEG_BIG;
        #pragma unroll
        for (int nt = 0; nt < 8; nt++) {
            mx0 = fmaxf(mx0, fmaxf(s[nt][0], s[nt][1]));
            mx1 = fmaxf(mx1, fmaxf(s[nt][2], s[nt][3]));
        }
        mx0 = fmaxf(mx0, __shfl_xor_sync(0xffffffffu, mx0, 1));
        mx0 = fmaxf(mx0, __shfl_xor_sync(0xffffffffu, mx0, 2));
        mx1 = fmaxf(mx1, __shfl_xor_sync(0xffffffffu, mx1, 1));
        mx1 = fmaxf(mx1, __shfl_xor_sync(0xffffffffu, mx1, 2));
        mx0 = fmaxf(mx0, m0r);
        mx1 = fmaxf(mx1, m1r);

        float sum0 = 0.f, sum1 = 0.f;
        #pragma unroll
        for (int nt = 0; nt < 8; nt++) {
            s[nt][0] = __expf(s[nt][0] - mx0);
            s[nt][1] = __expf(s[nt][1] - mx0);
            s[nt][2] = __expf(s[nt][2] - mx1);
            s[nt][3] = __expf(s[nt][3] - mx1);
            sum0 += s[nt][0] + s[nt][1];
            sum1 += s[nt][2] + s[nt][3];
        }
        sum0 += __shfl_xor_sync(0xffffffffu, sum0, 1);
        sum0 += __shfl_xor_sync(0xffffffffu, sum0, 2);
        sum1 += __shfl_xor_sync(0xffffffffu, sum1, 1);
        sum1 += __shfl_xor_sync(0xffffffffu, sum1, 2);

        float a0 = __expf(m0r - mx0);
        float a1 = __expf(m1r - mx1);
        l0 = l0 * a0 + sum0;
        l1 = l1 * a1 + sum1;
        m0r = mx0; m1r = mx1;
        #pragma unroll
        for (int nt = 0; nt < 8; nt++) {
            o[nt][0] *= a0; o[nt][1] *= a0;
            o[nt][2] *= a1; o[nt][3] *= a1;
        }

        // P -> smem as tf32 (warp-private rows)
        {
            const int r0 = wid * 16 + q;
            #pragma unroll
            for (int nt = 0; nt < 8; nt++) {
                const int c0 = nt * 8 + qi * 2;
                Ps[(r0    ) * PS_STR + c0    ] = f2tf32(s[nt][0]);
                Ps[(r0    ) * PS_STR + c0 + 1] = f2tf32(s[nt][1]);
                Ps[(r0 + 8) * PS_STR + c0    ] = f2tf32(s[nt][2]);
                Ps[(r0 + 8) * PS_STR + c0 + 1] = f2tf32(s[nt][3]);
            }
        }
        __syncwarp();

        // O += P * V
        {
            const int r0 = wid * 16 + q;
            #pragma unroll
            for (int ks = 0; ks < 8; ks++) {
                const int kk = ks * 8;
                unsigned int pa[4];
                pa[0] = Ps[(r0    ) * PS_STR + kk + qi    ];
                pa[1] = Ps[(r0 + 8) * PS_STR + kk + qi    ];
                pa[2] = Ps[(r0    ) * PS_STR + kk + qi + 4];
                pa[3] = Ps[(r0 + 8) * PS_STR + kk + qi + 4];
                #pragma unroll
                for (int nt = 0; nt < 8; nt++) {
                    unsigned int vb2[2];
                    vb2[0] = Vs[(kk + qi    ) * VS_STR + nt * 8 + q];
                    vb2[1] = Vs[(kk + qi + 4) * VS_STR + nt * 8 + q];
                    mma_tf32(o[nt], pa, vb2);
                }
            }
        }
        __syncwarp();   // PV reads of Ps done before next tile's P stores
    }

    // normalize and write out
    const float inv0 = 1.f / l0;
    const float inv1 = 1.f / l1;
    const size_t rg0 = (size_t)b * SEQ + q0 + wid * 16 + q;
    #pragma unroll
    for (int nt = 0; nt < 8; nt++) {
        const int c0 = nt * 8 + qi * 2;
        out[rg0 * HS + c0    ]       = o[nt][0] * inv0;
        out[rg0 * HS + c0 + 1]       = o[nt][1] * inv0;
        out[(rg0 + 8) * HS + c0    ] = o[nt][2] * inv1;
        out[(rg0 + 8) * HS + c0 + 1] = o[nt][3] * inv1;
    }
}

extern "C" void kernel_launch(void* const* d_in, const int* in_sizes, int n_in,
                              void* d_out, int out_size)
{
    const float* x  = (const float*)d_in[0];
    const float* Wq = (const float*)d_in[1];
    const float* Wk = (const float*)d_in[2];
    const float* Wv = (const float*)d_in[3];
    float* out = (float*)d_out;

    qkv_kernel<<<dim3(MTOT / 128, 3), 256>>>(x, Wq, Wk, Wv);

    (void)cudaFuncSetAttribute(attn_kernel,
                               cudaFuncAttributeMaxDynamicSharedMemorySize,
                               ATTN_SMEM);
    attn_kernel<<<dim3(SEQ / 64, BATCH), 128, ATTN_SMEM>>>(out);
}

// round 7
// speedup vs baseline: 4.3121x; 1.2219x over previous
#include <cuda_runtime.h>
#include <math.h>

#define BATCH 8
#define SEQ   2048
#define HID   1024
#define HS    64
#define MTOT  (BATCH*SEQ)
#define NQT   (SEQ/64)        // 32 q-tiles
#define NSPLIT 2

// q,k,v stored as tf32 bit patterns (q pre-scaled by 1024^-0.5)
__device__ unsigned int g_q[MTOT*HS];
__device__ unsigned int g_k[MTOT*HS];
__device__ unsigned int g_v[MTOT*HS];

// split-KV partials: [sp][b][qt][row][col], [sp][b][qt][row]
__device__ float g_po[NSPLIT*BATCH*NQT*64*64];
__device__ float g_pm[NSPLIT*BATCH*NQT*64];
__device__ float g_pl[NSPLIT*BATCH*NQT*64];

__device__ __forceinline__ unsigned int f2tf32(float f) {
    unsigned int u;
    asm("cvt.rna.tf32.f32 %0, %1;" : "=r"(u) : "f"(f));
    return u;
}

// D += A(16x8) * B(8x8), tf32 inputs, f32 accum
__device__ __forceinline__ void mma_tf32(float* d, const unsigned int* a,
                                         const unsigned int* b) {
    asm("mma.sync.aligned.m16n8k8.row.col.f32.tf32.tf32.f32 "
        "{%0,%1,%2,%3}, {%4,%5,%6,%7}, {%8,%9}, {%0,%1,%2,%3};"
        : "+f"(d[0]), "+f"(d[1]), "+f"(d[2]), "+f"(d[3])
        : "r"(a[0]), "r"(a[1]), "r"(a[2]), "r"(a[3]),
          "r"(b[0]), "r"(b[1]));
}

// ---------------------------------------------------------------------------
// QKV projection via tf32 MMA (unchanged from round 6, ~64us).
// ---------------------------------------------------------------------------
#define XS_STR 36
#define WS_STR 72

__global__ __launch_bounds__(256) void qkv_kernel(
    const float* __restrict__ x,
    const float* __restrict__ Wq,
    const float* __restrict__ Wk,
    const float* __restrict__ Wv)
{
    __shared__ unsigned int Xs[128 * XS_STR];
    __shared__ unsigned int Ws[32 * WS_STR];

    const float* W = (blockIdx.y == 0) ? Wq : (blockIdx.y == 1) ? Wk : Wv;
    unsigned int* out = (blockIdx.y == 0) ? g_q : (blockIdx.y == 1) ? g_k : g_v;

    const int t    = threadIdx.x;
    const int wid  = t >> 5;
    const int lane = t & 31;
    const int q    = lane >> 2;
    const int qi   = lane & 3;
    const int wm   = wid >> 1;
    const int wn   = wid & 1;
    const int m0   = blockIdx.x * 128;

    float acc[2][4][4];
    #pragma unroll
    for (int mt = 0; mt < 2; mt++)
        #pragma unroll
        for (int nt = 0; nt < 4; nt++)
            #pragma unroll
            for (int j = 0; j < 4; j++) acc[mt][nt][j] = 0.f;

    for (int k0 = 0; k0 < HID; k0 += 32) {
        #pragma unroll
        for (int rep = 0; rep < 4; rep++) {
            int lin = rep * 256 + t;
            int row = lin >> 3;
            int c4  = lin & 7;
            float4 v = *reinterpret_cast<const float4*>(
                &x[(size_t)(m0 + row) * HID + k0 + c4 * 4]);
            uint4 u = make_uint4(f2tf32(v.x), f2tf32(v.y),
                                 f2tf32(v.z), f2tf32(v.w));
            *reinterpret_cast<uint4*>(&Xs[row * XS_STR + c4 * 4]) = u;
        }
        #pragma unroll
        for (int rep = 0; rep < 2; rep++) {
            int lin = rep * 256 + t;
            int row = lin >> 4;
            int c4  = lin & 15;
            float4 v = *reinterpret_cast<const float4*>(
                &W[(size_t)(k0 + row) * HS + c4 * 4]);
            uint4 u = make_uint4(f2tf32(v.x), f2tf32(v.y),
                                 f2tf32(v.z), f2tf32(v.w));
            *reinterpret_cast<uint4*>(&Ws[row * WS_STR + c4 * 4]) = u;
        }
        __syncthreads();

        #pragma unroll
        for (int ks = 0; ks < 4; ks++) {
            const int kk = ks * 8;
            unsigned int a[2][4];
            #pragma unroll
            for (int mt = 0; mt < 2; mt++) {
                int r0 = wm * 32 + mt * 16;
                a[mt][0] = Xs[(r0 + q    ) * XS_STR + kk + qi    ];
                a[mt][1] = Xs[(r0 + q + 8) * XS_STR + kk + qi    ];
                a[mt][2] = Xs[(r0 + q    ) * XS_STR + kk + qi + 4];
                a[mt][3] = Xs[(r0 + q + 8) * XS_STR + kk + qi + 4];
            }
            #pragma unroll
            for (int nt = 0; nt < 4; nt++) {
                int n0 = wn * 32 + nt * 8;
                unsigned int b[2];
                b[0] = Ws[(kk + qi    ) * WS_STR + n0 + q];
                b[1] = Ws[(kk + qi + 4) * WS_STR + n0 + q];
                mma_tf32(acc[0][nt], a[0], b);
                mma_tf32(acc[1][nt], a[1], b);
            }
        }
        __syncthreads();
    }

    const float scl = (blockIdx.y == 0) ? 0.03125f : 1.0f;
    #pragma unroll
    for (int mt = 0; mt < 2; mt++) {
        int r0 = m0 + wm * 32 + mt * 16 + q;
        #pragma unroll
        for (int nt = 0; nt < 4; nt++) {
            int c0 = wn * 32 + nt * 8 + qi * 2;
            out[(size_t)r0 * HS + c0    ]       = f2tf32(acc[mt][nt][0] * scl);
            out[(size_t)r0 * HS + c0 + 1]       = f2tf32(acc[mt][nt][1] * scl);
            out[(size_t)(r0 + 8) * HS + c0    ] = f2tf32(acc[mt][nt][2] * scl);
            out[(size_t)(r0 + 8) * HS + c0 + 1] = f2tf32(acc[mt][nt][3] * scl);
        }
    }
}

// ---------------------------------------------------------------------------
// Causal flash attention, split-KV x2.  BQ=BK=64, 128 threads (4 warps x 16
// rows).  Q fragments in registers; P passed S->PV by register shuffles
// (no smem round-trip); partial (O,m,l) written to global, merged by
// combine_kernel.
// ---------------------------------------------------------------------------
#define KS_STR 68
#define VS_STR 72
#define NEG_BIG (-1e30f)

__global__ __launch_bounds__(128) void attn_kernel()
{
    __shared__ unsigned int Ks[64 * KS_STR];
    __shared__ unsigned int Vs[64 * VS_STR];

    const int t    = threadIdx.x;
    const int wid  = t >> 5;
    const int lane = t & 31;
    const int q    = lane >> 2;
    const int qi   = lane & 3;
    const int b    = blockIdx.y;
    const int xx   = blockIdx.x;          // 0..63, longest work first
    const int qt   = (NQT - 1) - (xx >> 1);
    const int sp   = xx & 1;
    const int ntile = qt + 1;
    const int half  = (ntile + 1) >> 1;
    const int js    = sp ? half : 0;
    const int je    = sp ? ntile : half;
    const int q0    = qt * 64;

    // stage Q tile via Ks, preload fragments
    {
        const unsigned int* qb = g_q + ((size_t)b * SEQ + q0) * HS;
        #pragma unroll
        for (int rep = 0; rep < 4; rep++) {
            int lin = rep * 128 + t;
            int row = lin >> 2;
            int c4  = lin & 3;
            *reinterpret_cast<uint4*>(&Ks[row * KS_STR + c4 * 16]) =
                *reinterpret_cast<const uint4*>(qb + row * HS + c4 * 16);
            *reinterpret_cast<uint4*>(&Ks[row * KS_STR + c4 * 16 + 4]) =
                *reinterpret_cast<const uint4*>(qb + row * HS + c4 * 16 + 4);
            *reinterpret_cast<uint4*>(&Ks[row * KS_STR + c4 * 16 + 8]) =
                *reinterpret_cast<const uint4*>(qb + row * HS + c4 * 16 + 8);
            *reinterpret_cast<uint4*>(&Ks[row * KS_STR + c4 * 16 + 12]) =
                *reinterpret_cast<const uint4*>(qb + row * HS + c4 * 16 + 12);
        }
    }
    __syncthreads();

    unsigned int qa[8][4];
    {
        const int r0 = wid * 16 + q;
        #pragma unroll
        for (int ks = 0; ks < 8; ks++) {
            const int kk = ks * 8;
            qa[ks][0] = Ks[(r0    ) * KS_STR + kk + qi    ];
            qa[ks][1] = Ks[(r0 + 8) * KS_STR + kk + qi    ];
            qa[ks][2] = Ks[(r0    ) * KS_STR + kk + qi + 4];
            qa[ks][3] = Ks[(r0 + 8) * KS_STR + kk + qi + 4];
        }
    }

    float o[8][4];
    #pragma unroll
    for (int nt = 0; nt < 8; nt++)
        #pragma unroll
        for (int j = 0; j < 4; j++) o[nt][j] = 0.f;
    float m0r = NEG_BIG, m1r = NEG_BIG, l0 = 0.f, l1 = 0.f;

    const int srcA = (lane & 0x1c) | (qi >> 1);   // 4q + qi/2
    const int srcB = srcA + 2;
    const bool odd = (qi & 1) != 0;

    for (int jt = js; jt < je; jt++) {
        const int kv0 = jt * 64;
        __syncthreads();   // prior tile reads (and Q staging reads) done

        {
            const unsigned int* kb = g_k + ((size_t)b * SEQ + kv0) * HS;
            const unsigned int* vb = g_v + ((size_t)b * SEQ + kv0) * HS;
            #pragma unroll
            for (int rep = 0; rep < 8; rep++) {
                int lin = rep * 128 + t;
                int row = lin >> 4;
                int c4  = lin & 15;
                *reinterpret_cast<uint4*>(&Ks[row * KS_STR + c4 * 4]) =
                    *reinterpret_cast<const uint4*>(kb + row * HS + c4 * 4);
                *reinterpret_cast<uint4*>(&Vs[row * VS_STR + c4 * 4]) =
                    *reinterpret_cast<const uint4*>(vb + row * HS + c4 * 4);
            }
        }
        __syncthreads();

        // S = Q * K^T : warp computes 16x64
        float s[8][4];
        #pragma unroll
        for (int nt = 0; nt < 8; nt++)
            #pragma unroll
            for (int j = 0; j < 4; j++) s[nt][j] = 0.f;

        #pragma unroll
        for (int ks = 0; ks < 8; ks++) {
            const int kk = ks * 8;
            #pragma unroll
            for (int nt = 0; nt < 8; nt++) {
                unsigned int kb2[2];
                kb2[0] = Ks[(nt * 8 + q) * KS_STR + kk + qi    ];
                kb2[1] = Ks[(nt * 8 + q) * KS_STR + kk + qi + 4];
                mma_tf32(s[nt], qa[ks], kb2);
            }
        }

        if (jt == qt) {   // causal mask (diagonal tile only)
            const int rg0 = q0 + wid * 16 + q;
            #pragma unroll
            for (int nt = 0; nt < 8; nt++) {
                const int cg = kv0 + nt * 8 + qi * 2;
                if (cg     > rg0    ) s[nt][0] = NEG_BIG;
                if (cg + 1 > rg0    ) s[nt][1] = NEG_BIG;
                if (cg     > rg0 + 8) s[nt][2] = NEG_BIG;
                if (cg + 1 > rg0 + 8) s[nt][3] = NEG_BIG;
            }
        }

        // online softmax on fragments (rows r0, r0+8)
        float mx0 = NEG_BIG, mx1 = NEG_BIG;
        #pragma unroll
        for (int nt = 0; nt < 8; nt++) {
            mx0 = fmaxf(mx0, fmaxf(s[nt][0], s[nt][1]));
            mx1 = fmaxf(mx1, fmaxf(s[nt][2], s[nt][3]));
        }
        mx0 = fmaxf(mx0, __shfl_xor_sync(0xffffffffu, mx0, 1));
        mx0 = fmaxf(mx0, __shfl_xor_sync(0xffffffffu, mx0, 2));
        mx1 = fmaxf(mx1, __shfl_xor_sync(0xffffffffu, mx1, 1));
        mx1 = fmaxf(mx1, __shfl_xor_sync(0xffffffffu, mx1, 2));
        mx0 = fmaxf(mx0, m0r);
        mx1 = fmaxf(mx1, m1r);

        float sum0 = 0.f, sum1 = 0.f;
        unsigned int pu[8][4];
        #pragma unroll
        for (int nt = 0; nt < 8; nt++) {
            s[nt][0] = __expf(s[nt][0] - mx0);
            s[nt][1] = __expf(s[nt][1] - mx0);
            s[nt][2] = __expf(s[nt][2] - mx1);
            s[nt][3] = __expf(s[nt][3] - mx1);
            sum0 += s[nt][0] + s[nt][1];
            sum1 += s[nt][2] + s[nt][3];
            pu[nt][0] = f2tf32(s[nt][0]);
            pu[nt][1] = f2tf32(s[nt][1]);
            pu[nt][2] = f2tf32(s[nt][2]);
            pu[nt][3] = f2tf32(s[nt][3]);
        }
        sum0 += __shfl_xor_sync(0xffffffffu, sum0, 1);
        sum0 += __shfl_xor_sync(0xffffffffu, sum0, 2);
        sum1 += __shfl_xor_sync(0xffffffffu, sum1, 1);
        sum1 += __shfl_xor_sync(0xffffffffu, sum1, 2);

        float a0 = __expf(m0r - mx0);
        float a1 = __expf(m1r - mx1);
        l0 = l0 * a0 + sum0;
        l1 = l1 * a1 + sum1;
        m0r = mx0; m1r = mx1;
        #pragma unroll
        for (int nt = 0; nt < 8; nt++) {
            o[nt][0] *= a0; o[nt][1] *= a0;
            o[nt][2] *= a1; o[nt][3] *= a1;
        }

        // O += P * V  (P fragments via register shuffle permute)
        #pragma unroll
        for (int ks = 0; ks < 8; ks++) {
            const int kk = ks * 8;
            unsigned int w0 = __shfl_sync(0xffffffffu, pu[ks][0], srcA);
            unsigned int w1 = __shfl_sync(0xffffffffu, pu[ks][1], srcA);
            unsigned int w2 = __shfl_sync(0xffffffffu, pu[ks][2], srcA);
            unsigned int w3 = __shfl_sync(0xffffffffu, pu[ks][3], srcA);
            unsigned int y0 = __shfl_sync(0xffffffffu, pu[ks][0], srcB);
            unsigned int y1 = __shfl_sync(0xffffffffu, pu[ks][1], srcB);
            unsigned int y2 = __shfl_sync(0xffffffffu, pu[ks][2], srcB);
            unsigned int y3 = __shfl_sync(0xffffffffu, pu[ks][3], srcB);
            unsigned int pa[4];
            pa[0] = odd ? w1 : w0;   // P[q   ][kk+qi]
            pa[1] = odd ? w3 : w2;   // P[q+8 ][kk+qi]
            pa[2] = odd ? y1 : y0;   // P[q   ][kk+qi+4]
            pa[3] = odd ? y3 : y2;   // P[q+8 ][kk+qi+4]
            #pragma unroll
            for (int nt = 0; nt < 8; nt++) {
                unsigned int vb2[2];
                vb2[0] = Vs[(kk + qi    ) * VS_STR + nt * 8 + q];
                vb2[1] = Vs[(kk + qi + 4) * VS_STR + nt * 8 + q];
                mma_tf32(o[nt], pa, vb2);
            }
        }
    }

    // write partial (O, m, l)
    {
        const int base = ((sp * BATCH + b) * NQT + qt) * 64;
        const int r0   = wid * 16 + q;
        float* po = &g_po[(size_t)base * 64];
        #pragma unroll
        for (int nt = 0; nt < 8; nt++) {
            const int c0 = nt * 8 + qi * 2;
            po[(r0    ) * 64 + c0    ] = o[nt][0];
            po[(r0    ) * 64 + c0 + 1] = o[nt][1];
            po[(r0 + 8) * 64 + c0    ] = o[nt][2];
            po[(r0 + 8) * 64 + c0 + 1] = o[nt][3];
        }
        if (qi == 0) {
            g_pm[base + r0    ] = m0r;
            g_pm[base + r0 + 8] = m1r;
            g_pl[base + r0    ] = l0;
            g_pl[base + r0 + 8] = l1;
        }
    }
}

// ---------------------------------------------------------------------------
// Merge the 2 split-KV partials and normalize.
// ---------------------------------------------------------------------------
__global__ __launch_bounds__(256) void combine_kernel(float* __restrict__ out)
{
    const int qt  = blockIdx.x;
    const int b   = blockIdx.y;
    const int t   = threadIdx.x;
    const int row = t >> 2;
    const int cs  = (t & 3) * 16;

    const int b0 = ((0 * BATCH + b) * NQT + qt) * 64;
    const int b1 = ((1 * BATCH + b) * NQT + qt) * 64;

    float m0 = g_pm[b0 + row], m1 = g_pm[b1 + row];
    float mx = fmaxf(m0, m1);
    float f0 = __expf(m0 - mx);
    float f1 = __expf(m1 - mx);
    float l  = g_pl[b0 + row] * f0 + g_pl[b1 + row] * f1;
    float inv = 1.f / l;

    const float* p0 = &g_po[(size_t)(b0 + row) * 64 + cs];
    const float* p1 = &g_po[(size_t)(b1 + row) * 64 + cs];
    float* op = &out[((size_t)b * SEQ + qt * 64 + row) * HS + cs];

    #pragma unroll
    for (int i = 0; i < 16; i += 4) {
        float4 a = *reinterpret_cast<const float4*>(p0 + i);
        float4 c = *reinterpret_cast<const float4*>(p1 + i);
        float4 r;
        r.x = (a.x * f0 + c.x * f1) * inv;
        r.y = (a.y * f0 + c.y * f1) * inv;
        r.z = (a.z * f0 + c.z * f1) * inv;
        r.w = (a.w * f0 + c.w * f1) * inv;
        *reinterpret_cast<float4*>(op + i) = r;
    }
}

extern "C" void kernel_launch(void* const* d_in, const int* in_sizes, int n_in,
                              void* d_out, int out_size)
{
    const float* x  = (const float*)d_in[0];
    const float* Wq = (const float*)d_in[1];
    const float* Wk = (const float*)d_in[2];
    const float* Wv = (const float*)d_in[3];
    float* out = (float*)d_out;

    qkv_kernel<<<dim3(MTOT / 128, 3), 256>>>(x, Wq, Wk, Wv);
    attn_kernel<<<dim3(NQT * NSPLIT, BATCH), 128>>>();
    combine_kernel<<<dim3(NQT, BATCH), 256>>>(out);
}